// round 3
// baseline (speedup 1.0000x reference)
#include <cuda_runtime.h>
#include <cstdint>

// ===========================================================================
// ChebyKANLinear: out[b,o] = sum_{i,d} T_d(tanh(x[b,i])) * coef[i,o,d]
//   B=8192, I=1024, O=1024, D+1=9
//
// Decomposition:
//   d=0: T_0 = 1  ->  bias[o] = sum_i coef[i,o,0]          (fp32, exact)
//   d=1..8: GEMM  out += A(8192 x 8192) @ Wt(8192 x 1024)  (tf32 mma, fp32 acc)
//     A[b, i*8+(d-1)] = T_d(tanh(x[b,i]))   (generated on the fly in SMEM)
//     Wt[i*8+(d-1), o] = round_tf32(coef[i,o,d])  (prologue transpose)
// ===========================================================================

#define BATCH   8192
#define IN_F    1024
#define OUT_F   1024
#define KTOT    8192          // I * 8  (d = 1..8)
#define BM      128           // CTA tile rows (batch)
#define BN      256           // CTA tile cols (out features)
#define KC      64            // K-chunk = 8 i-values * 8 degrees
#define SA      136           // As row stride (mod 32 == 8 -> conflict-free frags)
#define SB      264           // Bs row stride (mod 32 == 8 -> conflict-free frags)
#define NCHUNK  (KTOT / KC)   // 128

// Scratch (static device allocations; no runtime alloc per harness rules)
__device__ float g_Wt[(size_t)KTOT * OUT_F];   // tf32-rounded, [k][o], o contiguous
__device__ float g_Wt0[(size_t)IN_F * OUT_F];  // d=0 coefficients [i][o]
__device__ float g_part[8 * OUT_F];            // bias partial sums
__device__ float g_bias[OUT_F];

// --------------------------------------------------------------------------
__device__ __forceinline__ uint32_t f2tf32(float f) {
    uint32_t u;
    asm("cvt.rna.tf32.f32 %0, %1;" : "=r"(u) : "f"(f));
    return u;
}

__device__ __forceinline__ void cpa16(uint32_t dst, const void* src) {
    asm volatile("cp.async.cg.shared.global [%0], [%1], 16;\n" :: "r"(dst), "l"(src));
}
__device__ __forceinline__ void cpa_commit() { asm volatile("cp.async.commit_group;\n"); }
__device__ __forceinline__ void cpa_wait0()  { asm volatile("cp.async.wait_group 0;\n" ::: "memory"); }

__device__ __forceinline__ void mma8(float* c, const uint32_t* a, const uint32_t* b) {
    asm volatile(
        "mma.sync.aligned.m16n8k8.row.col.f32.tf32.tf32.f32 "
        "{%0,%1,%2,%3},{%4,%5,%6,%7},{%8,%9},{%0,%1,%2,%3};\n"
        : "+f"(c[0]), "+f"(c[1]), "+f"(c[2]), "+f"(c[3])
        : "r"(a[0]), "r"(a[1]), "r"(a[2]), "r"(a[3]), "r"(b[0]), "r"(b[1]));
}

// --------------------------------------------------------------------------
// Prologue 1: per-i transpose of coef[i, :, :] -> Wt rows i*8+0..7 (d=1..8)
// and Wt0[i][:] (d=0). Fully coalesced reads/writes; tf32 rounding applied
// here so the mainloop needs no per-iteration cvt on B.
// --------------------------------------------------------------------------
__global__ void __launch_bounds__(256) prep_kernel(const float* __restrict__ coef) {
    __shared__ float row[IN_F * 9];   // 9216 floats = 36 KB
    const int i = blockIdx.x;
    const float* src = coef + (size_t)i * (OUT_F * 9);
    #pragma unroll
    for (int q = threadIdx.x; q < OUT_F * 9; q += 256) row[q] = src[q];
    __syncthreads();

    #pragma unroll
    for (int r = 0; r < 32; r++) {               // 8192 outputs / 256 threads
        int id = threadIdx.x + (r << 8);
        int dd = id >> 10;                        // 0..7  (degree d-1)
        int o  = id & 1023;
        float v = row[o * 9 + dd + 1];            // coef[i][o][dd+1]
        g_Wt[(size_t)(((i << 3) + dd)) * OUT_F + o] = __uint_as_float(f2tf32(v));
    }
    #pragma unroll
    for (int r = 0; r < 4; r++) {
        int o = threadIdx.x + (r << 8);
        g_Wt0[(size_t)i * OUT_F + o] = row[o * 9];  // coef[i][o][0]
    }
}

// Prologue 2/3: bias[o] = sum_i coef[i,o,0]  (deterministic two-level tree)
__global__ void __launch_bounds__(256) bias_part_kernel() {
    int o  = (blockIdx.x << 8) + threadIdx.x;
    int i0 = blockIdx.y << 7;
    float s0 = 0.f, s1 = 0.f, s2 = 0.f, s3 = 0.f;
    #pragma unroll 8
    for (int i = 0; i < 128; i += 4) {
        s0 += g_Wt0[(size_t)(i0 + i + 0) * OUT_F + o];
        s1 += g_Wt0[(size_t)(i0 + i + 1) * OUT_F + o];
        s2 += g_Wt0[(size_t)(i0 + i + 2) * OUT_F + o];
        s3 += g_Wt0[(size_t)(i0 + i + 3) * OUT_F + o];
    }
    g_part[(blockIdx.y << 10) + o] = (s0 + s1) + (s2 + s3);
}

__global__ void __launch_bounds__(256) bias_red_kernel() {
    int o = (blockIdx.x << 8) + threadIdx.x;
    float s = 0.f;
    #pragma unroll
    for (int j = 0; j < 8; j++) s += g_part[(j << 10) + o];
    g_bias[o] = s;
}

// --------------------------------------------------------------------------
// Main fused GEMM.
//   CTA: 128(m) x 256(n), 8 warps (2x4), warp tile 64x64 (4 mi x 8 ni of
//   m16n8k8), K-chunk 64 (8 i-values), double-buffered cp.async on B and x.
//   As stored [k][m] stride 136; Bs stored [k][n] stride 264. Both strides
//   are ==8 (mod 32) so fragment LDS banks are t*8+g -> all 32 distinct.
// --------------------------------------------------------------------------
__global__ void __launch_bounds__(256) cheby_main(const float* __restrict__ X,
                                                  float* __restrict__ Out) {
    extern __shared__ float sm[];
    float* As  = sm;                        // [KC][SA]   (single buffer)
    float* Bs0 = sm + KC * SA;              // [KC][SB]   x2
    float* Bs1 = Bs0 + KC * SB;
    float* Xs0 = Bs1 + KC * SB;             // [BM][8]    x2
    float* Xs1 = Xs0 + BM * 8;

    const int tid  = threadIdx.x;
    const int lane = tid & 31;
    const int w    = tid >> 5;
    const int wm   = w >> 2;                // 0..1
    const int wn   = w & 3;                 // 0..3
    const int g    = lane >> 2;             // 0..7
    const int t    = lane & 3;              // 0..3
    const int bm   = blockIdx.y << 7;
    const int bn   = blockIdx.x << 8;

    const uint32_t as_base = (uint32_t)__cvta_generic_to_shared(As);
    const uint32_t bs_base0 = (uint32_t)__cvta_generic_to_shared(Bs0);
    const uint32_t bs_base1 = (uint32_t)__cvta_generic_to_shared(Bs1);
    const uint32_t xs_base0 = (uint32_t)__cvta_generic_to_shared(Xs0);
    const uint32_t xs_base1 = (uint32_t)__cvta_generic_to_shared(Xs1);
    (void)as_base;

    float acc[4][8][4];
    #pragma unroll
    for (int mi = 0; mi < 4; mi++)
        #pragma unroll
        for (int ni = 0; ni < 8; ni++)
            #pragma unroll
            for (int q = 0; q < 4; q++) acc[mi][ni][q] = 0.f;

    const int rowb = tid >> 1;              // x-loader mapping (128 rows x 2)
    const int half = tid & 1;

    // ---- prefetch chunk 0 ----
    {
        cpa16(xs_base0 + (uint32_t)(((rowb << 3) + (half << 2)) << 2),
              X + (size_t)(bm + rowb) * IN_F + (half << 2));
        #pragma unroll
        for (int r = 0; r < 16; r++) {
            int q  = tid + (r << 8);
            int kr = q >> 6, seg = q & 63;
            cpa16(bs_base0 + (uint32_t)((kr * SB + (seg << 2)) << 2),
                  g_Wt + (size_t)kr * OUT_F + bn + (seg << 2));
        }
        cpa_commit();
    }

    for (int c = 0; c < NCHUNK; c++) {
        const int p = c & 1;
        cpa_wait0();
        __syncthreads();   // buf[p] (x + B) visible to all threads

        // prefetch chunk c+1 into buf[p^1] (overlaps with gen + MMA below)
        if (c + 1 < NCHUNK) {
            const uint32_t xsn = p ? xs_base0 : xs_base1;
            const uint32_t bsn = p ? bs_base0 : bs_base1;
            cpa16(xsn + (uint32_t)(((rowb << 3) + (half << 2)) << 2),
                  X + (size_t)(bm + rowb) * IN_F + ((c + 1) << 3) + (half << 2));
            #pragma unroll
            for (int r = 0; r < 16; r++) {
                int q  = tid + (r << 8);
                int kr = q >> 6, seg = q & 63;
                cpa16(bsn + (uint32_t)((kr * SB + (seg << 2)) << 2),
                      g_Wt + (size_t)(((c + 1) << 6) + kr) * OUT_F + bn + (seg << 2));
            }
            cpa_commit();
        }

        // ---- A generation: T_1..T_8 of tanh(x) for 128 rows x 8 i's ----
        {
            const float* xsrc = p ? Xs1 : Xs0;
            uint32_t* Au = (uint32_t*)As;
            #pragma unroll
            for (int j = 0; j < 4; j++) {
                int pi = tid + (j << 8);
                int b  = pi & 127;
                int il = pi >> 7;
                float xv = xsrc[(b << 3) + il];
                // robust tanh: accurate under fast-math, no approx-tanh error
                float e  = __expf(2.f * xv);
                float tv = 1.f - 2.f / (e + 1.f);
                int kc2 = il << 3;
                Au[kc2 * SA + b] = f2tf32(tv);        // T_1
                float Tm2 = 1.f, Tm1 = tv;
                #pragma unroll
                for (int d = 2; d <= 8; d++) {
                    float T = 2.f * tv * Tm1 - Tm2;
                    Au[(kc2 + d - 1) * SA + b] = f2tf32(T);
                    Tm2 = Tm1; Tm1 = T;
                }
            }
        }
        __syncthreads();   // As ready for MMA

        // ---- MMA: 8 k8-steps x (4 mi x 8 ni) ----
        const uint32_t* Bu  = (const uint32_t*)(p ? Bs1 : Bs0);
        const uint32_t* Au2 = (const uint32_t*)As;
        #pragma unroll
        for (int s = 0; s < 8; s++) {
            const int k = (s << 3) + t;
            uint32_t a[4][4];
            #pragma unroll
            for (int mi = 0; mi < 4; mi++) {
                int base = k * SA + (wm << 6) + (mi << 4) + g;
                a[mi][0] = Au2[base];
                a[mi][1] = Au2[base + 8];
                a[mi][2] = Au2[base + 4 * SA];
                a[mi][3] = Au2[base + 4 * SA + 8];
            }
            uint32_t bb[8][2];
            #pragma unroll
            for (int ni = 0; ni < 8; ni++) {
                int base = k * SB + (wn << 6) + (ni << 3) + g;
                bb[ni][0] = Bu[base];
                bb[ni][1] = Bu[base + 4 * SB];
            }
            #pragma unroll
            for (int mi = 0; mi < 4; mi++)
                #pragma unroll
                for (int ni = 0; ni < 8; ni++)
                    mma8(acc[mi][ni], a[mi], bb[ni]);
        }
    }

    // ---- epilogue: add bias (d=0 term), store fp32 ----
    #pragma unroll
    for (int ni = 0; ni < 8; ni++) {
        const int cc = bn + (wn << 6) + (ni << 3) + (t << 1);
        const float2 bv = *reinterpret_cast<const float2*>(g_bias + cc);
        #pragma unroll
        for (int mi = 0; mi < 4; mi++) {
            const int r0 = bm + (wm << 6) + (mi << 4) + g;
            float2 o0 = { acc[mi][ni][0] + bv.x, acc[mi][ni][1] + bv.y };
            float2 o1 = { acc[mi][ni][2] + bv.x, acc[mi][ni][3] + bv.y };
            *reinterpret_cast<float2*>(Out + (size_t)r0 * OUT_F + cc)       = o0;
            *reinterpret_cast<float2*>(Out + (size_t)(r0 + 8) * OUT_F + cc) = o1;
        }
    }
}

// --------------------------------------------------------------------------
extern "C" void kernel_launch(void* const* d_in, const int* in_sizes, int n_in,
                              void* d_out, int out_size) {
    (void)in_sizes; (void)n_in; (void)out_size;
    const float* x    = (const float*)d_in[0];
    const float* coef = (const float*)d_in[1];
    float* out        = (float*)d_out;

    const int smem_bytes = (KC * SA + 2 * KC * SB + 2 * BM * 8) * 4;  // 178176
    cudaFuncSetAttribute(cheby_main, cudaFuncAttributeMaxDynamicSharedMemorySize,
                         smem_bytes);

    prep_kernel<<<IN_F, 256>>>(coef);
    bias_part_kernel<<<dim3(4, 8), 256>>>();
    bias_red_kernel<<<4, 256>>>();
    cheby_main<<<dim3(OUT_F / BN, BATCH / BM), 256, smem_bytes>>>(x, out);
}

// round 5
// speedup vs baseline: 1.0323x; 1.0323x over previous
#include <cuda_runtime.h>
#include <cstdint>

// ===========================================================================
// ChebyKANLinear, legacy mma.sync m16n8k8 tf32 path (tcgen05 is blocked by
// the harness's PTX target). Fragment-packed operands end-to-end:
//   B: prep kernel permutes coef into exact B-fragment order in global mem
//   A: Chebyshev generator writes STS.128 directly in A-fragment layout
// ===========================================================================

#define BATCH   8192
#define IN_F    1024
#define OUT_F   1024
#define BM      128
#define BN      256
#define KC      64            // 8 i-values * 8 degrees per chunk
#define NCHUNK  128           // IN_F / 8
#define A_BYTES 32768         // BM * KC * 4
#define B_BYTES 65536         // BN * KC * 4

// Static device scratch (no runtime allocation allowed)
__device__ float g_BF[(size_t)NCHUNK * 16 * 4096];  // B fragments, 32 MB
__device__ float g_Wt0[(size_t)IN_F * OUT_F];       // d=0 coefficients [i][o]
__device__ float g_T[(size_t)BATCH * IN_F];         // tanh(x)
__device__ float g_part[8 * OUT_F];
__device__ float g_bias[OUT_F];

// ---------------------------------------------------------------- utils
__device__ __forceinline__ uint32_t f2tf32(float f) {
    uint32_t u;
    asm("cvt.rna.tf32.f32 %0, %1;" : "=r"(u) : "f"(f));
    return u;
}
__device__ __forceinline__ float tf32r(float f) { return __uint_as_float(f2tf32(f)); }

__device__ __forceinline__ void cpa16(uint32_t dst, const void* src) {
    asm volatile("cp.async.cg.shared.global [%0], [%1], 16;\n" :: "r"(dst), "l"(src));
}
__device__ __forceinline__ void cpa_commit() { asm volatile("cp.async.commit_group;\n"); }
template <int N>
__device__ __forceinline__ void cpa_wait() {
    asm volatile("cp.async.wait_group %0;\n" :: "n"(N) : "memory");
}

__device__ __forceinline__ void lds128(uint4& v, uint32_t addr) {
    asm volatile("ld.shared.v4.b32 {%0,%1,%2,%3}, [%4];"
                 : "=r"(v.x), "=r"(v.y), "=r"(v.z), "=r"(v.w) : "r"(addr));
}
__device__ __forceinline__ void sts128(uint32_t addr, uint32_t a, uint32_t b,
                                       uint32_t c, uint32_t d) {
    asm volatile("st.shared.v4.b32 [%0], {%1,%2,%3,%4};"
                 :: "r"(addr), "r"(a), "r"(b), "r"(c), "r"(d));
}

__device__ __forceinline__ void mma8(float* c, const uint4& a, uint32_t b0, uint32_t b1) {
    asm volatile(
        "mma.sync.aligned.m16n8k8.row.col.f32.tf32.tf32.f32 "
        "{%0,%1,%2,%3},{%4,%5,%6,%7},{%8,%9},{%0,%1,%2,%3};\n"
        : "+f"(c[0]), "+f"(c[1]), "+f"(c[2]), "+f"(c[3])
        : "r"(a.x), "r"(a.y), "r"(a.z), "r"(a.w), "r"(b0), "r"(b1));
}

// A-fragment lane swizzle (proved conflict-free for both STS.128 gen writes
// and LDS.128 consumer reads)
__device__ __forceinline__ uint32_t a_lswz(uint32_t lane_c) {
    return (lane_c * 16u) ^ (((lane_c >> 3) & 3u) << 4);
}

// ---------------------------------------------------------------- prologues
// coef[i][o][d] -> g_BF in B-fragment order; g_Wt0[i][o] = coef[i][o][0].
// Per (c=i>>3, wnG=o>>6) block of 4096 floats:
//   word = (s*4 + nip)*128 + (g*4+t)*4 + parity*2 + reg
//   with s=i&7, nip=(o>>4)&3, parity=(o>>3)&1, g=o&7, t=(d-1)&3, reg=(d-1)>>2
__global__ void __launch_bounds__(256) prep_kernel(const float* __restrict__ coef) {
    __shared__ float frag[8192];   // per-i slice: [wnG16][nip4][lane32][4]
    const int i = blockIdx.x;
    const int c = i >> 3, s = i & 7;
    #pragma unroll
    for (int r = 0; r < 4; r++) {
        const int o = threadIdx.x + (r << 8);
        const float* cr = coef + (size_t)i * 9216 + (size_t)o * 9;
        float cv[9];
        #pragma unroll
        for (int d = 0; d < 9; d++) cv[d] = __ldg(cr + d);
        const int g = o & 7, par = (o >> 3) & 1, nip = (o >> 4) & 3, wnG = o >> 6;
        const int base = (wnG * 4 + nip) * 128 + par * 2;
        #pragma unroll
        for (int d = 1; d <= 8; d++) {
            const int tq = (d - 1) & 3, reg = (d - 1) >> 2;
            frag[base + (g * 4 + tq) * 4 + reg] = tf32r(cv[d]);
        }
        g_Wt0[(size_t)i * OUT_F + o] = cv[0];
    }
    __syncthreads();
    float4* dst = reinterpret_cast<float4*>(g_BF);
    const float4* src = reinterpret_cast<const float4*>(frag);
    #pragma unroll
    for (int k = 0; k < 8; k++) {
        const int fi4 = threadIdx.x + (k << 8);
        const int wnG = fi4 >> 7, rem = fi4 & 127;   // rem = nip*32 + lane
        dst[(size_t)(c * 16 + wnG) * 1024 + s * 128 + rem] = src[fi4];
    }
}

__global__ void __launch_bounds__(256) tanh_kernel(const float* __restrict__ X) {
    size_t q = ((size_t)blockIdx.x << 8) + threadIdx.x;   // float4 index
    float4 v = reinterpret_cast<const float4*>(X)[q];
    float4 o;
    { float e = __expf(2.f * v.x); o.x = 1.f - 2.f / (e + 1.f); }
    { float e = __expf(2.f * v.y); o.y = 1.f - 2.f / (e + 1.f); }
    { float e = __expf(2.f * v.z); o.z = 1.f - 2.f / (e + 1.f); }
    { float e = __expf(2.f * v.w); o.w = 1.f - 2.f / (e + 1.f); }
    reinterpret_cast<float4*>(g_T)[q] = o;
}

__global__ void __launch_bounds__(256) bias_part_kernel() {
    int o = (blockIdx.x << 8) + threadIdx.x;
    int i0 = blockIdx.y << 7;
    float s0 = 0.f, s1 = 0.f, s2 = 0.f, s3 = 0.f;
    #pragma unroll 8
    for (int i = 0; i < 128; i += 4) {
        s0 += g_Wt0[(size_t)(i0 + i + 0) * OUT_F + o];
        s1 += g_Wt0[(size_t)(i0 + i + 1) * OUT_F + o];
        s2 += g_Wt0[(size_t)(i0 + i + 2) * OUT_F + o];
        s3 += g_Wt0[(size_t)(i0 + i + 3) * OUT_F + o];
    }
    g_part[(blockIdx.y << 10) + o] = (s0 + s1) + (s2 + s3);
}
__global__ void __launch_bounds__(256) bias_red_kernel() {
    int o = (blockIdx.x << 8) + threadIdx.x;
    float s = 0.f;
    #pragma unroll
    for (int j = 0; j < 8; j++) s += g_part[(j << 10) + o];
    g_bias[o] = s;
}

// ---------------------------------------------------------------- main GEMM
// 256 threads = 8 warps (2 wm x 4 wn), warp tile 64x64.
// SMEM: A frags 32KB (single buffer) + B frags 2x64KB (double buffer).
__global__ void __launch_bounds__(256, 1) cheby_main(float* __restrict__ Out) {
    extern __shared__ uint8_t sm[];
    const uint32_t smA = (uint32_t)__cvta_generic_to_shared(sm);
    const uint32_t smB = smA + A_BYTES;

    const int tid  = threadIdx.x;
    const int lane = tid & 31;
    const int w    = tid >> 5;
    const int wm   = w >> 2;           // 0..1
    const int wn   = w & 3;            // 0..3
    const int g    = lane >> 2;
    const int t    = lane & 3;
    const int bm   = blockIdx.y << 7;
    const int bx   = blockIdx.x;
    const int bn   = bx << 8;

    float acc[4][8][4];
    #pragma unroll
    for (int mi = 0; mi < 4; mi++)
        #pragma unroll
        for (int ni = 0; ni < 8; ni++)
            #pragma unroll
            for (int q = 0; q < 4; q++) acc[mi][ni][q] = 0.f;

    // --- generator unit constants (2 units per thread) ---
    int il[2];
    uint32_t genAddr[2][4];
    const float* rowLo[2];
    const float* rowHi[2];
    #pragma unroll
    for (int k = 0; k < 2; k++) {
        const int u = tid + (k << 8);
        il[k] = u >> 6;
        const int p = u & 63;
        const int wmU = p >> 5, miU = (p >> 3) & 3, gU = p & 7;
        const uint32_t blockBase = (uint32_t)(((il[k] * 2 + wmU) * 4 + miU) * 512);
        #pragma unroll
        for (int tq = 0; tq < 4; tq++)
            genAddr[k][tq] = smA + blockBase + a_lswz((uint32_t)(gU * 4 + tq));
        const int mU = (wmU << 6) + (miU << 4) + gU;
        rowLo[k] = g_T + (size_t)(bm + mU) * IN_F;
        rowHi[k] = rowLo[k] + (size_t)8 * IN_F;
    }

    // --- B cp.async source (contiguous per chunk) ---
    const float4* bsrc = reinterpret_cast<const float4*>(g_BF) + (size_t)bx * 4096;
    // per chunk c: src = bsrc + c*16384 + j,  j in [0,4096)

    // prefetch B(0)
    #pragma unroll
    for (int k = 0; k < 16; k++) {
        const int j = tid + (k << 8);
        cpa16(smB + (uint32_t)(j * 16), bsrc + j);
    }
    cpa_commit();

    // tanh values for chunk 0
    float tvc[4], tvn[4];
    #pragma unroll
    for (int k = 0; k < 2; k++) {
        tvc[2 * k]     = rowLo[k][il[k]];
        tvc[2 * k + 1] = rowHi[k][il[k]];
    }

    const uint32_t lsw = a_lswz((uint32_t)lane);
    const uint32_t aBaseW = smA + (uint32_t)(wm * 2048);
    const uint32_t bBaseW = (uint32_t)(wn * 16384 + lane * 16);

    for (int c = 0; c < NCHUNK; c++) {
        const int stage = c & 1;

        // prefetch B(c+1) into the other buffer
        if (c + 1 < NCHUNK) {
            const float4* src = bsrc + (size_t)(c + 1) * 16384;
            const uint32_t dstB = smB + (uint32_t)((stage ^ 1) * B_BYTES);
            #pragma unroll
            for (int k = 0; k < 16; k++) {
                const int j = tid + (k << 8);
                cpa16(dstB + (uint32_t)(j * 16), src + j);
            }
            cpa_commit();
        }

        // --- generate A fragments for chunk c ---
        #pragma unroll
        for (int k = 0; k < 2; k++) {
            const float tl = tvc[2 * k], th = tvc[2 * k + 1];
            float Tl[8], Th[8];
            Tl[0] = tl; Th[0] = th;
            Tl[1] = 2.f * tl * tl - 1.f;
            Th[1] = 2.f * th * th - 1.f;
            #pragma unroll
            for (int d = 2; d < 8; d++) {
                Tl[d] = 2.f * tl * Tl[d - 1] - Tl[d - 2];
                Th[d] = 2.f * th * Th[d - 1] - Th[d - 2];
            }
            #pragma unroll
            for (int tq = 0; tq < 4; tq++)
                sts128(genAddr[k][tq], f2tf32(Tl[tq]), f2tf32(Th[tq]),
                       f2tf32(Tl[tq + 4]), f2tf32(Th[tq + 4]));
        }

        // prefetch tanh values for chunk c+1
        if (c + 1 < NCHUNK) {
            const int col = (c + 1) << 3;
            #pragma unroll
            for (int k = 0; k < 2; k++) {
                tvn[2 * k]     = rowLo[k][col + il[k]];
                tvn[2 * k + 1] = rowHi[k][col + il[k]];
            }
        }

        if (c + 1 < NCHUNK) cpa_wait<1>(); else cpa_wait<0>();
        __syncthreads();   // A written + B(stage) resident

        // --- MMA: 8 k8-steps, register-pipelined A fragments ---
        const uint32_t bBase = smB + (uint32_t)(stage * B_BYTES) + bBaseW;
        uint4 aC[4], aN[4];
        #pragma unroll
        for (int mi = 0; mi < 4; mi++)
            lds128(aC[mi], aBaseW + (uint32_t)(mi * 512) + lsw);

        #pragma unroll
        for (int s = 0; s < 8; s++) {
            uint4 bC[4];
            #pragma unroll
            for (int nip = 0; nip < 4; nip++)
                lds128(bC[nip], bBase + (uint32_t)(s * 2048 + nip * 512));
            if (s < 7) {
                #pragma unroll
                for (int mi = 0; mi < 4; mi++)
                    lds128(aN[mi], aBaseW + (uint32_t)((s + 1) * 4096 + mi * 512) + lsw);
            }
            #pragma unroll
            for (int ni = 0; ni < 8; ni++) {
                const uint32_t b0 = (ni & 1) ? bC[ni >> 1].z : bC[ni >> 1].x;
                const uint32_t b1 = (ni & 1) ? bC[ni >> 1].w : bC[ni >> 1].y;
                #pragma unroll
                for (int mi = 0; mi < 4; mi++)
                    mma8(acc[mi][ni], aC[mi], b0, b1);
            }
            if (s < 7) {
                #pragma unroll
                for (int mi = 0; mi < 4; mi++) aC[mi] = aN[mi];
            }
        }
        __syncthreads();   // A consumed before next gen overwrites it

        #pragma unroll
        for (int q = 0; q < 4; q++) tvc[q] = tvn[q];
    }

    // --- epilogue: add bias (d=0 term), store fp32 ---
    #pragma unroll
    for (int ni = 0; ni < 8; ni++) {
        const int cc = bn + (wn << 6) + (ni << 3) + (t << 1);
        const float2 bv = *reinterpret_cast<const float2*>(g_bias + cc);
        #pragma unroll
        for (int mi = 0; mi < 4; mi++) {
            const int r0 = bm + (wm << 6) + (mi << 4) + g;
            float2 o0 = { acc[mi][ni][0] + bv.x, acc[mi][ni][1] + bv.y };
            float2 o1 = { acc[mi][ni][2] + bv.x, acc[mi][ni][3] + bv.y };
            *reinterpret_cast<float2*>(Out + (size_t)r0 * OUT_F + cc)       = o0;
            *reinterpret_cast<float2*>(Out + (size_t)(r0 + 8) * OUT_F + cc) = o1;
        }
    }
}

// --------------------------------------------------------------------------
extern "C" void kernel_launch(void* const* d_in, const int* in_sizes, int n_in,
                              void* d_out, int out_size) {
    (void)in_sizes; (void)n_in; (void)out_size;
    const float* x    = (const float*)d_in[0];
    const float* coef = (const float*)d_in[1];
    float* out        = (float*)d_out;

    const int smem_bytes = A_BYTES + 2 * B_BYTES;   // 163840
    cudaFuncSetAttribute(cheby_main, cudaFuncAttributeMaxDynamicSharedMemorySize,
                         smem_bytes);

    prep_kernel<<<IN_F, 256>>>(coef);
    tanh_kernel<<<(BATCH * IN_F) / (256 * 4), 256>>>(x);
    bias_part_kernel<<<dim3(4, 8), 256>>>();
    bias_red_kernel<<<4, 256>>>();
    cheby_main<<<dim3(OUT_F / BN, BATCH / BM), 256, smem_bytes>>>(out);
}